// round 6
// baseline (speedup 1.0000x reference)
#include <cuda_runtime.h>
#include <math.h>

#define NN   131072
#define EE   131071
#define DD   128
#define FF0  384
#define K0N  91751
#define K1N  45876

static __device__ __forceinline__ float lrelu(float x){ return x > 0.f ? x : 0.2f * x; }
static __device__ __forceinline__ unsigned ordf(float f){
    unsigned u = __float_as_uint(f);
    return (u & 0x80000000u) ? ~u : (u | 0x80000000u);
}
static __device__ __forceinline__ float unordf(unsigned u){
    unsigned v = (u & 0x80000000u) ? (u & 0x7fffffffu) : ~u;
    return __uint_as_float(v);
}

// ------------------------- scratch (static device globals) -------------------------
__device__ float    g_xh0[NN * FF0];
__device__ float    g_h0 [NN * FF0];
__device__ float    g_als0[NN * 3], g_ald0[NN * 3];
__device__ unsigned g_mx0[NN * 3];
__device__ float    g_den0[NN * 3];
__device__ float    g_score0[NN];
__device__ unsigned g_key0[NN];
__device__ float    g_bnsum[FF0], g_bnsq[FF0];
__device__ float    g_scale[FF0], g_shift[FF0];
__device__ float    g_pinv;
__device__ unsigned g_hist[65536];
__device__ unsigned g_binhi, g_abovehi, g_binlo, g_abovelo;
__device__ unsigned g_T;
__device__ int      g_r;
__device__ unsigned g_eq;
__device__ int      g_flags[NN];
__device__ int      g_partial[256];
__device__ int      g_nm[NN];
__device__ float    g_h0p[K0N * FF0];
__device__ float    g_xh1[K0N * DD];
__device__ float    g_h1 [K0N * DD];
__device__ float    g_als1[K0N], g_ald1[K0N];
__device__ unsigned g_mx1[K0N];
__device__ float    g_den1[K0N];
__device__ int      g_es1[EE], g_ed1[EE];
__device__ float    g_score1[K0N];
__device__ unsigned g_key1[K0N];
__device__ unsigned g_gmax[DD];

// ------------------------- GEMM: C[M,N] = A[M,K] @ B[K,N], row-major -------------------------
// BM=128, BN=64, BK=16, 256 threads, 8x4 per-thread microtile. N%64==0, K%16==0 required.
__global__ void gemm_kernel(const float* __restrict__ A, const float* __restrict__ B,
                            float* __restrict__ C, int M, int N, int K)
{
    __shared__ float As[16][132];
    __shared__ float Bs[16][68];

    const int rowBase = blockIdx.y * 128;
    const int colBase = blockIdx.x * 64;
    const int tid = threadIdx.x;
    const int ty = tid >> 4;      // 0..15
    const int tx = tid & 15;      // 0..15

    float acc[8][4];
#pragma unroll
    for (int i = 0; i < 8; i++)
#pragma unroll
        for (int j = 0; j < 4; j++) acc[i][j] = 0.f;

    for (int kk = 0; kk < K; kk += 16) {
        // load A tile: 128x16 = 512 float4
#pragma unroll
        for (int j = 0; j < 2; j++) {
            int f4  = tid * 2 + j;        // 0..511
            int row = f4 >> 2;            // 0..127
            int k4  = (f4 & 3) * 4;       // 0,4,8,12
            int grow = rowBase + row;
            float4 av = make_float4(0.f, 0.f, 0.f, 0.f);
            if (grow < M)
                av = *(const float4*)(A + (size_t)grow * K + kk + k4);
            As[k4 + 0][row] = av.x;
            As[k4 + 1][row] = av.y;
            As[k4 + 2][row] = av.z;
            As[k4 + 3][row] = av.w;
        }
        // load B tile: 16x64 = 256 float4
        {
            int k  = tid >> 4;            // 0..15
            int n4 = (tid & 15) * 4;      // 0..60
            float4 bv = *(const float4*)(B + (size_t)(kk + k) * N + colBase + n4);
            *(float4*)&Bs[k][n4] = bv;
        }
        __syncthreads();

#pragma unroll
        for (int k = 0; k < 16; k++) {
            float4 a0 = *(float4*)&As[k][ty * 8];
            float4 a1 = *(float4*)&As[k][ty * 8 + 4];
            float4 b0 = *(float4*)&Bs[k][tx * 4];
            float aa[8] = {a0.x, a0.y, a0.z, a0.w, a1.x, a1.y, a1.z, a1.w};
            float bb[4] = {b0.x, b0.y, b0.z, b0.w};
#pragma unroll
            for (int i = 0; i < 8; i++)
#pragma unroll
                for (int j = 0; j < 4; j++)
                    acc[i][j] += aa[i] * bb[j];
        }
        __syncthreads();
    }

#pragma unroll
    for (int i = 0; i < 8; i++) {
        int grow = rowBase + ty * 8 + i;
        if (grow < M)
            *(float4*)(C + (size_t)grow * N + colBase + tx * 4) =
                make_float4(acc[i][0], acc[i][1], acc[i][2], acc[i][3]);
    }
}

// ------------------------- GAT attention init (per node) -------------------------
// computes al_src/al_dst, zeroes output accumulator row, inits segment-max with
// the self-loop logit, zeroes denominator.
__global__ void att_init(const float* __restrict__ xh, const float* __restrict__ av,
                         const float* __restrict__ dv, float* als, float* ald,
                         unsigned* mx, float* den, float* hz, int H)
{
    int n = blockIdx.x, t = threadIdx.x;
    int F = H * 128;
    float ps[3] = {0.f, 0.f, 0.f}, pd[3] = {0.f, 0.f, 0.f};
    for (int h = 0; h < H; h++) {
        float v = xh[(size_t)n * F + h * 128 + t];
        ps[h] = v * av[h * 128 + t];
        pd[h] = v * dv[h * 128 + t];
        hz[(size_t)n * F + h * 128 + t] = 0.f;
    }
    __shared__ float red[6][128];
#pragma unroll
    for (int q = 0; q < 3; q++) { red[q][t] = ps[q]; red[3 + q][t] = pd[q]; }
    __syncthreads();
    for (int off = 64; off > 0; off >>= 1) {
        if (t < off)
#pragma unroll
            for (int q = 0; q < 6; q++) red[q][t] += red[q][t + off];
        __syncthreads();
    }
    if (t < H) {
        float a = red[t][0], d = red[3 + t][0];
        als[n * H + t] = a;
        ald[n * H + t] = d;
        float l = lrelu(a + d);
        mx[n * H + t] = ordf(l);
        den[n * H + t] = 0.f;
    }
}

// mode 0: skip edges with s==d (layer 0 raw edges). mode 1: skip s<0 (remapped edges).
__global__ void edge_max(const int* __restrict__ s, const int* __restrict__ d, int E,
                         const float* __restrict__ als, const float* __restrict__ ald,
                         unsigned* mx, int H, int mode)
{
    int i = blockIdx.x * blockDim.x + threadIdx.x;
    if (i >= E) return;
    int ss = s[i], dd = d[i];
    if (mode == 0) { if (ss == dd) return; } else { if (ss < 0) return; }
    for (int h = 0; h < H; h++) {
        float l = lrelu(als[ss * H + h] + ald[dd * H + h]);
        atomicMax(&mx[dd * H + h], ordf(l));
    }
}

__global__ void edge_den(const int* __restrict__ s, const int* __restrict__ d, int E, int Nn,
                         const float* __restrict__ als, const float* __restrict__ ald,
                         const unsigned* __restrict__ mx, float* den, int H, int mode)
{
    int i = blockIdx.x * blockDim.x + threadIdx.x;
    if (i >= E + Nn) return;
    int ss, dd;
    if (i < E) {
        ss = s[i]; dd = d[i];
        if (mode == 0) { if (ss == dd) return; } else { if (ss < 0) return; }
    } else {
        ss = dd = i - E;
    }
    for (int h = 0; h < H; h++) {
        float l = lrelu(als[ss * H + h] + ald[dd * H + h]);
        atomicAdd(&den[dd * H + h], expf(l - unordf(mx[dd * H + h])));
    }
}

// one block (128 threads) per edge/self-loop: out[dst] += xh[src] * alpha
__global__ void edge_acc(const int* __restrict__ s, const int* __restrict__ d, int E, int Nn,
                         const float* __restrict__ als, const float* __restrict__ ald,
                         const unsigned* __restrict__ mx, const float* __restrict__ den,
                         const float* __restrict__ xh, float* out, int H, int mode)
{
    int e = blockIdx.x, t = threadIdx.x;
    int F = H * 128;
    int ss, dd;
    if (e < E) {
        ss = s[e]; dd = d[e];
        if (mode == 0) { if (ss == dd) return; } else { if (ss < 0) return; }
    } else {
        ss = dd = e - E;
    }
    __shared__ float alpha[3];
    if (t < H) {
        float l = lrelu(als[ss * H + t] + ald[dd * H + t]);
        alpha[t] = expf(l - unordf(mx[dd * H + t])) / den[dd * H + t];
    }
    __syncthreads();
    for (int h = 0; h < H; h++)
        atomicAdd(&out[(size_t)dd * F + h * 128 + t],
                  xh[(size_t)ss * F + h * 128 + t] * alpha[h]);
}

__global__ void zero_bn(float* a, float* b, int F)
{
    int t = threadIdx.x;
    if (t < F) { a[t] = 0.f; b[t] = 0.f; }
}

// tanh(h + bias), accumulate per-channel BN sums. blockDim = F, 64 rows per block.
__global__ void epi_bn(float* h, const float* __restrict__ bias,
                       float* bnsum, float* bnsq, int Ntot, int F)
{
    int c = threadIdx.x;
    int r0 = blockIdx.x * 64;
    float s = 0.f, q = 0.f;
    float bc = bias[c];
    for (int r = 0; r < 64; r++) {
        int row = r0 + r;
        if (row >= Ntot) break;
        float v = tanhf(h[(size_t)row * F + c] + bc);
        h[(size_t)row * F + c] = v;
        s += v; q += v * v;
    }
    atomicAdd(&bnsum[c], s);
    atomicAdd(&bnsq[c], q);
}

// BN scale/shift, 1/||p||, zero hist, optionally init gmax. 1 block, 512 threads.
__global__ void bn_final(const float* bnsum, const float* bnsq,
                         const float* __restrict__ g, const float* __restrict__ be,
                         float* scale, float* shift, const float* __restrict__ p,
                         float* pinv, unsigned* hist, unsigned* gmax, int F, float invN)
{
    int t = threadIdx.x;
    __shared__ float psq[512];
    float acc = 0.f;
    for (int c = t; c < F; c += blockDim.x) {
        float mu  = bnsum[c] * invN;
        float var = bnsq[c] * invN - mu * mu;
        float sc  = g[c] * rsqrtf(var + 1e-5f);
        scale[c] = sc;
        shift[c] = be[c] - mu * sc;
        acc += p[c] * p[c];
    }
    psq[t] = acc;
    __syncthreads();
    if (t == 0) {
        float s = 0.f;
        for (int i = 0; i < 512; i++) s += psq[i];
        *pinv = rsqrtf(s);
    }
    for (int i = t; i < 65536; i += blockDim.x) hist[i] = 0u;
    if (gmax != 0 && t < 128) gmax[t] = 0u;
}

// apply BN in place, compute score = tanh(dot(h_bn, p)/||p||) and its ordered key
__global__ void score_kernel(float* h, const float* __restrict__ scale,
                             const float* __restrict__ shift, const float* __restrict__ p,
                             const float* __restrict__ pinv,
                             float* score, unsigned* key, int F)
{
    int n = blockIdx.x, t = threadIdx.x;
    float dot = 0.f;
    int FW = F / 128;
    for (int u = 0; u < FW; u++) {
        int c = u * 128 + t;
        float v = h[(size_t)n * F + c] * scale[c] + shift[c];
        h[(size_t)n * F + c] = v;
        dot += v * p[c];
    }
    __shared__ float red[128];
    red[t] = dot;
    __syncthreads();
    for (int off = 64; off > 0; off >>= 1) {
        if (t < off) red[t] += red[t + off];
        __syncthreads();
    }
    if (t == 0) {
        float sc = tanhf(red[0] * (*pinv));
        score[n] = sc;
        key[n] = ordf(sc);
    }
}

__global__ void hist_hi(const unsigned* __restrict__ key, int Ntot, unsigned* hist)
{
    int i = blockIdx.x * blockDim.x + threadIdx.x;
    if (i < Ntot) atomicAdd(&hist[key[i] >> 16], 1u);
}

__global__ void hist_lo(const unsigned* __restrict__ key, int Ntot, unsigned* hist,
                        const unsigned* __restrict__ binhi)
{
    int i = blockIdx.x * blockDim.x + threadIdx.x;
    if (i < Ntot) {
        unsigned k = key[i];
        if ((k >> 16) == *binhi) atomicAdd(&hist[k & 0xFFFFu], 1u);
    }
}

// single block, 1024 threads, 65536 bins. Finds the bin containing the K-th
// largest key; zeroes the histogram for the next use. On the "lo" pass it also
// finalizes the exact 32-bit threshold T and equals-count r.
__global__ void find_bin(unsigned* hist, int Ktarget, const unsigned* prevAbove,
                         unsigned* outBin, unsigned* outAbove,
                         const unsigned* hiBin, unsigned* outT, int* outR, unsigned* eqZ)
{
    int t = threadIdx.x;
    __shared__ unsigned csum[1024];
    __shared__ unsigned suffixAfter[1024];
    int base = t * 64;
    unsigned s = 0;
    for (int i = 0; i < 64; i++) s += hist[base + i];
    csum[t] = s;
    __syncthreads();
    if (t == 0) {
        unsigned run = 0;
        for (int j = 1023; j >= 0; j--) { suffixAfter[j] = run; run += csum[j]; }
    }
    __syncthreads();
    int K = Ktarget - (prevAbove ? (int)(*prevAbove) : 0);
    unsigned run = suffixAfter[t];
    for (int i = 63; i >= 0; i--) {
        int bin = base + i;
        unsigned above = run;          // count of keys strictly above this bin
        run += hist[bin];              // count of keys >= this bin
        if ((int)above < K && (int)run >= K) {
            *outBin = (unsigned)bin;
            *outAbove = above;
            if (outT) {
                *outT = ((*hiBin) << 16) | (unsigned)bin;
                *outR = K - (int)above;
                *eqZ = 0u;
            }
        }
    }
    __syncthreads();
    for (int i = 0; i < 64; i++) hist[base + i] = 0u;
}

__global__ void flags_kernel(const unsigned* __restrict__ key, int Ntot,
                             const unsigned* __restrict__ Tp, const int* __restrict__ rp,
                             unsigned* eq, int* flags)
{
    int i = blockIdx.x * blockDim.x + threadIdx.x;
    if (i >= Ntot) return;
    unsigned k = key[i], T = *Tp;
    int f = 0;
    if (k > T) f = 1;
    else if (k == T) { if ((int)atomicAdd(eq, 1u) < *rp) f = 1; }
    flags[i] = f;
}

__global__ void scan_partial(const int* __restrict__ flags, int Ntot, int* partial)
{
    __shared__ int sh[1024];
    int i = blockIdx.x * 1024 + threadIdx.x;
    sh[threadIdx.x] = (i < Ntot) ? flags[i] : 0;
    __syncthreads();
    for (int off = 512; off > 0; off >>= 1) {
        if (threadIdx.x < off) sh[threadIdx.x] += sh[threadIdx.x + off];
        __syncthreads();
    }
    if (threadIdx.x == 0) partial[blockIdx.x] = sh[0];
}

__global__ void scan_offsets(int* partial, int nb)
{
    if (threadIdx.x == 0) {
        int run = 0;
        for (int i = 0; i < nb; i++) { int v = partial[i]; partial[i] = run; run += v; }
    }
}

__global__ void scan_apply(const int* __restrict__ flags, int Ntot,
                           const int* __restrict__ partial, int* nm)
{
    __shared__ int sh[1024];
    int t = threadIdx.x;
    int i = blockIdx.x * 1024 + t;
    int f = (i < Ntot) ? flags[i] : 0;
    sh[t] = f;
    __syncthreads();
    for (int off = 1; off < 1024; off <<= 1) {
        int v = (t >= off) ? sh[t - off] : 0;
        __syncthreads();
        sh[t] += v;
        __syncthreads();
    }
    if (i < Ntot) nm[i] = f ? (partial[blockIdx.x] + sh[t] - f) : -1;
}

// pool0 gather: h0p[new] = relu(h0[n] * score0[n])
__global__ void gather0(const float* __restrict__ h, const float* __restrict__ score,
                        const int* __restrict__ nm, float* hp)
{
    int n = blockIdx.x, t = threadIdx.x;
    int m = nm[n];
    if (m < 0) return;
    float sc = score[n];
#pragma unroll
    for (int u = 0; u < 3; u++) {
        int c = u * 128 + t;
        float v = h[(size_t)n * FF0 + c] * sc;
        hp[(size_t)m * FF0 + c] = fmaxf(v, 0.f);
    }
}

__global__ void remap_edges(const int* __restrict__ src, const int* __restrict__ dst,
                            const int* __restrict__ nm, int* es, int* ed)
{
    int e = blockIdx.x * blockDim.x + threadIdx.x;
    if (e >= EE) return;
    int s = src[e], d = dst[e];
    int ns = -1, nd = -1;
    if (s != d) { ns = nm[s]; nd = nm[d]; }
    if (ns >= 0 && nd >= 0) { es[e] = ns; ed[e] = nd; }
    else { es[e] = -1; ed[e] = -1; }
}

// pool1 + global max fused: gmax[c] = max over selected n of h1[n,c]*score1[n]
__global__ void maxreduce(const float* __restrict__ h1, const float* __restrict__ score,
                          const int* __restrict__ flags, unsigned* gmax)
{
    int t = threadIdx.x;
    int base = blockIdx.x * 64;
    float lm = -3.402823e38f;
    for (int r = 0; r < 64; r++) {
        int n = base + r;
        if (n >= K0N) break;
        if (flags[n]) lm = fmaxf(lm, h1[(size_t)n * DD + t] * score[n]);
    }
    atomicMax(&gmax[t], ordf(lm));
}

// final MLP: relu(max) -> relu(@Wm1+bm1) -> @Wm2+bm2. 1 block, 256 threads.
__global__ void mlp_kernel(const unsigned* __restrict__ gmax,
                           const float* __restrict__ Wm1, const float* __restrict__ bm1,
                           const float* __restrict__ Wm2, const float* __restrict__ bm2,
                           float* out)
{
    __shared__ float v[128], mid[256];
    int t = threadIdx.x;
    if (t < 128) v[t] = fmaxf(unordf(gmax[t]), 0.f);
    __syncthreads();
    float a = bm1[t];
    for (int c = 0; c < 128; c++) a += v[c] * Wm1[c * 256 + t];
    mid[t] = fmaxf(a, 0.f);
    __syncthreads();
    if (t < 128) {
        float o = bm2[t];
        for (int j = 0; j < 256; j++) o += mid[j] * Wm2[j * 128 + t];
        out[t] = o;
    }
}

// ------------------------------------------------------------------
extern "C" void kernel_launch(void* const* d_in, const int* in_sizes, int n_in,
                              void* d_out, int out_size)
{
    (void)in_sizes; (void)n_in; (void)out_size;
    const float* x   = (const float*)d_in[0];
    const int*   ei  = (const int*)  d_in[1];
    const float* W0  = (const float*)d_in[3];
    const float* as0 = (const float*)d_in[4];
    const float* ad0 = (const float*)d_in[5];
    const float* b0  = (const float*)d_in[6];
    const float* g0  = (const float*)d_in[7];
    const float* be0 = (const float*)d_in[8];
    const float* p0  = (const float*)d_in[9];
    const float* W1  = (const float*)d_in[10];
    const float* as1 = (const float*)d_in[11];
    const float* ad1 = (const float*)d_in[12];
    const float* b1  = (const float*)d_in[13];
    const float* g1  = (const float*)d_in[14];
    const float* be1 = (const float*)d_in[15];
    const float* p1  = (const float*)d_in[16];
    const float* Wm1 = (const float*)d_in[17];
    const float* bm1 = (const float*)d_in[18];
    const float* Wm2 = (const float*)d_in[19];
    const float* bm2 = (const float*)d_in[20];
    const int* src = ei;
    const int* dst = ei + EE;
    float* out = (float*)d_out;

    float *xh0, *h0, *als0, *ald0, *den0, *score0, *bnsum, *bnsq, *scale, *shift, *pinv;
    float *h0p, *xh1, *h1, *als1, *ald1, *den1, *score1;
    unsigned *mx0, *key0, *hist, *binhiP, *abovehiP, *binloP, *abovloP, *TP, *eqP, *mx1, *key1, *gmax;
    int *rP, *flags, *partial, *nm, *es1, *ed1;

    cudaGetSymbolAddress((void**)&xh0, g_xh0);
    cudaGetSymbolAddress((void**)&h0, g_h0);
    cudaGetSymbolAddress((void**)&als0, g_als0);
    cudaGetSymbolAddress((void**)&ald0, g_ald0);
    cudaGetSymbolAddress((void**)&mx0, g_mx0);
    cudaGetSymbolAddress((void**)&den0, g_den0);
    cudaGetSymbolAddress((void**)&score0, g_score0);
    cudaGetSymbolAddress((void**)&key0, g_key0);
    cudaGetSymbolAddress((void**)&bnsum, g_bnsum);
    cudaGetSymbolAddress((void**)&bnsq, g_bnsq);
    cudaGetSymbolAddress((void**)&scale, g_scale);
    cudaGetSymbolAddress((void**)&shift, g_shift);
    cudaGetSymbolAddress((void**)&pinv, g_pinv);
    cudaGetSymbolAddress((void**)&hist, g_hist);
    cudaGetSymbolAddress((void**)&binhiP, g_binhi);
    cudaGetSymbolAddress((void**)&abovehiP, g_abovehi);
    cudaGetSymbolAddress((void**)&binloP, g_binlo);
    cudaGetSymbolAddress((void**)&abovloP, g_abovelo);
    cudaGetSymbolAddress((void**)&TP, g_T);
    cudaGetSymbolAddress((void**)&rP, g_r);
    cudaGetSymbolAddress((void**)&eqP, g_eq);
    cudaGetSymbolAddress((void**)&flags, g_flags);
    cudaGetSymbolAddress((void**)&partial, g_partial);
    cudaGetSymbolAddress((void**)&nm, g_nm);
    cudaGetSymbolAddress((void**)&h0p, g_h0p);
    cudaGetSymbolAddress((void**)&xh1, g_xh1);
    cudaGetSymbolAddress((void**)&h1, g_h1);
    cudaGetSymbolAddress((void**)&als1, g_als1);
    cudaGetSymbolAddress((void**)&ald1, g_ald1);
    cudaGetSymbolAddress((void**)&mx1, g_mx1);
    cudaGetSymbolAddress((void**)&den1, g_den1);
    cudaGetSymbolAddress((void**)&es1, g_es1);
    cudaGetSymbolAddress((void**)&ed1, g_ed1);
    cudaGetSymbolAddress((void**)&score1, g_score1);
    cudaGetSymbolAddress((void**)&key1, g_key1);
    cudaGetSymbolAddress((void**)&gmax, g_gmax);

    // ---- GAT layer 0 ----
    {
        dim3 grid(FF0 / 64, NN / 128);
        gemm_kernel<<<grid, 256>>>(x, W0, xh0, NN, FF0, DD);
    }
    att_init<<<NN, 128>>>(xh0, as0, ad0, als0, ald0, mx0, den0, h0, 3);
    edge_max<<<(EE + 255) / 256, 256>>>(src, dst, EE, als0, ald0, mx0, 3, 0);
    edge_den<<<(EE + NN + 255) / 256, 256>>>(src, dst, EE, NN, als0, ald0, mx0, den0, 3, 0);
    edge_acc<<<EE + NN, 128>>>(src, dst, EE, NN, als0, ald0, mx0, den0, xh0, h0, 3, 0);
    zero_bn<<<1, FF0>>>(bnsum, bnsq, FF0);
    epi_bn<<<(NN + 63) / 64, FF0>>>(h0, b0, bnsum, bnsq, NN, FF0);
    bn_final<<<1, 512>>>(bnsum, bnsq, g0, be0, scale, shift, p0, pinv, hist,
                         (unsigned*)0, FF0, 1.0f / (float)NN);
    score_kernel<<<NN, 128>>>(h0, scale, shift, p0, pinv, score0, key0, FF0);

    // ---- TopK pool 0 (exact K0 selection via 2-level radix histogram) ----
    hist_hi<<<(NN + 255) / 256, 256>>>(key0, NN, hist);
    find_bin<<<1, 1024>>>(hist, K0N, (const unsigned*)0, binhiP, abovehiP,
                          (const unsigned*)0, (unsigned*)0, (int*)0, (unsigned*)0);
    hist_lo<<<(NN + 255) / 256, 256>>>(key0, NN, hist, binhiP);
    find_bin<<<1, 1024>>>(hist, K0N, abovehiP, binloP, abovloP, binhiP, TP, rP, eqP);
    flags_kernel<<<(NN + 255) / 256, 256>>>(key0, NN, TP, rP, eqP, flags);
    scan_partial<<<NN / 1024, 1024>>>(flags, NN, partial);
    scan_offsets<<<1, 32>>>(partial, NN / 1024);
    scan_apply<<<NN / 1024, 1024>>>(flags, NN, partial, nm);
    gather0<<<NN, 128>>>(h0, score0, nm, h0p);
    remap_edges<<<(EE + 255) / 256, 256>>>(src, dst, nm, es1, ed1);

    // ---- GAT layer 1 ----
    {
        dim3 grid(DD / 64, (K0N + 127) / 128);
        gemm_kernel<<<grid, 256>>>(h0p, W1, xh1, K0N, DD, FF0);
    }
    att_init<<<K0N, 128>>>(xh1, as1, ad1, als1, ald1, mx1, den1, h1, 1);
    edge_max<<<(EE + 255) / 256, 256>>>(es1, ed1, EE, als1, ald1, mx1, 1, 1);
    edge_den<<<(EE + K0N + 255) / 256, 256>>>(es1, ed1, EE, K0N, als1, ald1, mx1, den1, 1, 1);
    edge_acc<<<EE + K0N, 128>>>(es1, ed1, EE, K0N, als1, ald1, mx1, den1, xh1, h1, 1, 1);
    zero_bn<<<1, DD>>>(bnsum, bnsq, DD);
    epi_bn<<<(K0N + 63) / 64, DD>>>(h1, b1, bnsum, bnsq, K0N, DD);
    bn_final<<<1, 512>>>(bnsum, bnsq, g1, be1, scale, shift, p1, pinv, hist,
                         gmax, DD, 1.0f / (float)K0N);
    score_kernel<<<K0N, 128>>>(h1, scale, shift, p1, pinv, score1, key1, DD);

    // ---- TopK pool 1 (selection only) + fused global max ----
    hist_hi<<<(K0N + 255) / 256, 256>>>(key1, K0N, hist);
    find_bin<<<1, 1024>>>(hist, K1N, (const unsigned*)0, binhiP, abovehiP,
                          (const unsigned*)0, (unsigned*)0, (int*)0, (unsigned*)0);
    hist_lo<<<(K0N + 255) / 256, 256>>>(key1, K0N, hist, binhiP);
    find_bin<<<1, 1024>>>(hist, K1N, abovehiP, binloP, abovloP, binhiP, TP, rP, eqP);
    flags_kernel<<<(K0N + 255) / 256, 256>>>(key1, K0N, TP, rP, eqP, flags);
    maxreduce<<<(K0N + 63) / 64, 128>>>(h1, score1, flags, gmax);

    // ---- MLP head ----
    mlp_kernel<<<1, 256>>>(gmax, Wm1, bm1, Wm2, bm2, out);
}

// round 7
// speedup vs baseline: 1.0503x; 1.0503x over previous
#include <cuda_runtime.h>
#include <math.h>

#define NN   131072
#define EE   131071
#define DD   128
#define FF0  384
#define K0N  91751
#define K1N  45876

static __device__ __forceinline__ float lrelu(float x){ return x > 0.f ? x : 0.2f * x; }
static __device__ __forceinline__ unsigned ordf(float f){
    unsigned u = __float_as_uint(f);
    return (u & 0x80000000u) ? ~u : (u | 0x80000000u);
}
static __device__ __forceinline__ float unordf(unsigned u){
    unsigned v = (u & 0x80000000u) ? (u & 0x7fffffffu) : ~u;
    return __uint_as_float(v);
}
// fast tanh: abs err ~1e-7, sign-exact, monotone enough for scoring
static __device__ __forceinline__ float ftanh(float x){
    float ax = fminf(fabsf(x) * 2.f, 88.f);
    float e  = __expf(ax);
    float r  = __fdividef(e - 1.f, e + 1.f);
    return __uint_as_float(__float_as_uint(r) | (__float_as_uint(x) & 0x80000000u));
}
static __device__ __forceinline__ void red_add_v4(float* p, float4 v){
    asm volatile("red.global.add.v4.f32 [%0], {%1, %2, %3, %4};"
                 :: "l"(p), "f"(v.x), "f"(v.y), "f"(v.z), "f"(v.w) : "memory");
}

// ------------------------- scratch (static device globals) -------------------------
__device__ float    g_xh0[NN * FF0];
__device__ float    g_h0 [NN * FF0];
__device__ float    g_als0[NN * 3], g_ald0[NN * 3];
__device__ float    g_den0[NN * 3];
__device__ float    g_score0[NN];
__device__ unsigned g_key0[NN];
__device__ float    g_bnsum[FF0], g_bnsq[FF0];
__device__ float    g_scale[FF0], g_shift[FF0];
__device__ float    g_q[FF0];
__device__ float    g_c0;
__device__ float    g_pinv;
__device__ unsigned g_hist[65536];
__device__ unsigned g_binhi, g_abovehi, g_binlo, g_abovelo;
__device__ unsigned g_T;
__device__ int      g_r;
__device__ unsigned g_eq;
__device__ int      g_flags[NN];
__device__ int      g_partial[256];
__device__ int      g_nm[NN];
__device__ float    g_h0p[K0N * FF0];
__device__ float    g_xh1[K0N * DD];
__device__ float    g_h1 [K0N * DD];
__device__ float    g_als1[K0N], g_ald1[K0N];
__device__ float    g_den1[K0N];
__device__ int      g_es1[EE], g_ed1[EE];
__device__ float    g_score1[K0N];
__device__ unsigned g_key1[K0N];
__device__ unsigned g_gmax[DD];

// ------------------------- GEMM: C[M,N] = A[M,K] @ B[K,N], row-major -------------------------
// BM=128, BN=128, BK=8, 256 threads, 8x8 per-thread microtile. N%128==0, K%8==0 required.
__global__ void gemm_kernel(const float* __restrict__ A, const float* __restrict__ B,
                            float* __restrict__ C, int M, int N, int K)
{
    __shared__ float As[8][128];
    __shared__ float Bs[8][128];

    const int tid = threadIdx.x;
    const int rowBase = blockIdx.y * 128;
    const int colBase = blockIdx.x * 128;
    const int tx = tid & 15, ty = tid >> 4;
    const int ar = tid >> 1, ah = (tid & 1) * 4;
    const int bk = tid >> 5, bn = (tid & 31) * 4;

    float acc[8][8];
#pragma unroll
    for (int i = 0; i < 8; i++)
#pragma unroll
        for (int j = 0; j < 8; j++) acc[i][j] = 0.f;

    for (int kk = 0; kk < K; kk += 8) {
        float4 av = make_float4(0.f, 0.f, 0.f, 0.f);
        if (rowBase + ar < M)
            av = *(const float4*)(A + (size_t)(rowBase + ar) * K + kk + ah);
        As[ah + 0][ar] = av.x;
        As[ah + 1][ar] = av.y;
        As[ah + 2][ar] = av.z;
        As[ah + 3][ar] = av.w;
        *(float4*)&Bs[bk][bn] = *(const float4*)(B + (size_t)(kk + bk) * N + colBase + bn);
        __syncthreads();

#pragma unroll
        for (int k = 0; k < 8; k++) {
            float a[8], b[8];
            *(float4*)&a[0] = *(float4*)&As[k][ty * 8];
            *(float4*)&a[4] = *(float4*)&As[k][ty * 8 + 4];
            *(float4*)&b[0] = *(float4*)&Bs[k][tx * 8];
            *(float4*)&b[4] = *(float4*)&Bs[k][tx * 8 + 4];
#pragma unroll
            for (int i = 0; i < 8; i++)
#pragma unroll
                for (int j = 0; j < 8; j++)
                    acc[i][j] += a[i] * b[j];
        }
        __syncthreads();
    }

#pragma unroll
    for (int i = 0; i < 8; i++) {
        int row = rowBase + ty * 8 + i;
        if (row < M) {
            *(float4*)(C + (size_t)row * N + colBase + tx * 8) =
                make_float4(acc[i][0], acc[i][1], acc[i][2], acc[i][3]);
            *(float4*)(C + (size_t)row * N + colBase + tx * 8 + 4) =
                make_float4(acc[i][4], acc[i][5], acc[i][6], acc[i][7]);
        }
    }
}

// ------------------------- GAT attention init (per node) -------------------------
// computes al_src/al_dst, and directly seeds the UNNORMALIZED aggregation with the
// self-loop term: h0[n] = w_self * xh[n], den[n] = w_self  (w = exp(leakyrelu(logit))).
__global__ void att_init(const float* __restrict__ xh, const float* __restrict__ av,
                         const float* __restrict__ dv, float* als, float* ald,
                         float* den, float* h0, int H)
{
    int n = blockIdx.x, t = threadIdx.x;
    int lane = t & 31, w = t >> 5;
    int F = H << 7;
    float vv[3] = {0.f, 0.f, 0.f};
    float pr[6] = {0.f, 0.f, 0.f, 0.f, 0.f, 0.f};
    for (int h = 0; h < H; h++) {
        float v = xh[(size_t)n * F + h * 128 + t];
        vv[h] = v;
        pr[h]     = v * av[h * 128 + t];
        pr[3 + h] = v * dv[h * 128 + t];
    }
#pragma unroll
    for (int off = 16; off; off >>= 1)
        for (int h = 0; h < H; h++) {
            pr[h]     += __shfl_down_sync(0xffffffffu, pr[h], off);
            pr[3 + h] += __shfl_down_sync(0xffffffffu, pr[3 + h], off);
        }
    __shared__ float sred[6][4];
    __shared__ float wsh[3];
    if (lane == 0)
        for (int h = 0; h < H; h++) { sred[h][w] = pr[h]; sred[3 + h][w] = pr[3 + h]; }
    __syncthreads();
    if (t < H) {
        float a = sred[t][0] + sred[t][1] + sred[t][2] + sred[t][3];
        float d = sred[3 + t][0] + sred[3 + t][1] + sred[3 + t][2] + sred[3 + t][3];
        als[n * H + t] = a;
        ald[n * H + t] = d;
        float wv = __expf(lrelu(a + d));
        wsh[t] = wv;
        den[n * H + t] = wv;
    }
    __syncthreads();
    for (int h = 0; h < H; h++)
        h0[(size_t)n * F + h * 128 + t] = vv[h] * wsh[h];
}

// fused edge pass: one warp per edge. den[dst] += w; h0[dst] += w * xh[src] (vector RED).
// mode 0: skip s==d (raw edges). mode 1: skip s<0 (remapped edges).
__global__ void edge_fused(const int* __restrict__ s, const int* __restrict__ d, int E,
                           const float* __restrict__ als, const float* __restrict__ ald,
                           const float* __restrict__ xh, float* out, float* den,
                           int H, int mode)
{
    int e = blockIdx.x * 8 + (threadIdx.x >> 5);
    int lane = threadIdx.x & 31;
    if (e >= E) return;
    int ss = s[e], dd = d[e];
    if (mode == 0) { if (ss == dd) return; } else { if (ss < 0) return; }
    float w = 0.f;
    if (lane < H) {
        w = __expf(lrelu(als[ss * H + lane] + ald[dd * H + lane]));
        atomicAdd(&den[dd * H + lane], w);
    }
    int F = H << 7;
    const float4* sp = (const float4*)(xh + (size_t)ss * F);
    float* op = out + (size_t)dd * F;
    for (int h = 0; h < H; h++) {
        float wh = __shfl_sync(0xffffffffu, w, h);
        float4 v = sp[h * 32 + lane];
        v.x *= wh; v.y *= wh; v.z *= wh; v.w *= wh;
        red_add_v4(op + (h * 32 + lane) * 4, v);
    }
}

__global__ void zero_bn(float* a, float* b, int F)
{
    int t = threadIdx.x;
    if (t < F) { a[t] = 0.f; b[t] = 0.f; }
}

// normalize (divide by den), +bias, tanh; accumulate per-channel BN sums.
__global__ void epi_bn(float* h, const float* __restrict__ den, const float* __restrict__ bias,
                       float* bnsum, float* bnsq, int Ntot, int F, int H)
{
    int c = threadIdx.x;
    int hh = c >> 7;
    int r0 = blockIdx.x * 64;
    float s = 0.f, q = 0.f;
    float bc = bias[c];
    for (int r = 0; r < 64; r++) {
        int row = r0 + r;
        if (row >= Ntot) break;
        float dn = den[row * H + hh];
        float v = ftanh(__fdividef(h[(size_t)row * F + c], dn) + bc);
        h[(size_t)row * F + c] = v;
        s += v; q += v * v;
    }
    atomicAdd(&bnsum[c], s);
    atomicAdd(&bnsq[c], q);
}

// BN scale/shift + folded score vector q = scale*p, c0 = dot(shift,p), pinv = 1/||p||.
// 1 block, 512 threads.
__global__ void bn_final(const float* bnsum, const float* bnsq,
                         const float* __restrict__ g, const float* __restrict__ be,
                         float* scale, float* shift, const float* __restrict__ p,
                         float* pinv, float* qv, float* c0out, unsigned* gmax,
                         int F, float invN)
{
    int t = threadIdx.x;
    __shared__ float psq[512], pc0[512];
    float accp = 0.f, accc = 0.f;
    for (int c = t; c < F; c += 512) {
        float mu  = bnsum[c] * invN;
        float var = bnsq[c] * invN - mu * mu;
        float sc  = g[c] * rsqrtf(var + 1e-5f);
        float sh  = be[c] - mu * sc;
        scale[c] = sc;
        shift[c] = sh;
        float pc = p[c];
        qv[c] = sc * pc;
        accp += pc * pc;
        accc += sh * pc;
    }
    psq[t] = accp; pc0[t] = accc;
    __syncthreads();
    for (int off = 256; off > 0; off >>= 1) {
        if (t < off) { psq[t] += psq[t + off]; pc0[t] += pc0[t + off]; }
        __syncthreads();
    }
    if (t == 0) { *pinv = rsqrtf(psq[0]); *c0out = pc0[0]; }
    if (gmax != 0 && t < 128) gmax[t] = 0u;
}

// read-only score: score = tanh((dot(h_tanh, q) + c0) * pinv)
__global__ void score_kernel(const float* __restrict__ h, const float* __restrict__ qv,
                             const float* __restrict__ c0p, const float* __restrict__ pinv,
                             float* score, unsigned* key, int F)
{
    int n = blockIdx.x, t = threadIdx.x;
    float dot = 0.f;
    int FW = F >> 7;
    for (int u = 0; u < FW; u++) {
        int c = u * 128 + t;
        dot += h[(size_t)n * F + c] * qv[c];
    }
    __shared__ float red[128];
    red[t] = dot;
    __syncthreads();
    for (int off = 64; off > 0; off >>= 1) {
        if (t < off) red[t] += red[t + off];
        __syncthreads();
    }
    if (t == 0) {
        float sc = ftanh((red[0] + *c0p) * (*pinv));
        score[n] = sc;
        key[n] = ordf(sc);
    }
}

__global__ void hist_hi(const unsigned* __restrict__ key, int Ntot, unsigned* hist)
{
    int i = blockIdx.x * blockDim.x + threadIdx.x;
    if (i < Ntot) atomicAdd(&hist[key[i] >> 16], 1u);
}

__global__ void hist_lo(const unsigned* __restrict__ key, int Ntot, unsigned* hist,
                        const unsigned* __restrict__ binhi)
{
    int i = blockIdx.x * blockDim.x + threadIdx.x;
    if (i < Ntot) {
        unsigned k = key[i];
        if ((k >> 16) == *binhi) atomicAdd(&hist[k & 0xFFFFu], 1u);
    }
}

// single block, 1024 threads, 65536 bins; parallel suffix scan; zeroes hist after use.
__global__ void find_bin(unsigned* hist, int Ktarget, const unsigned* prevAbove,
                         unsigned* outBin, unsigned* outAbove,
                         const unsigned* hiBin, unsigned* outT, int* outR, unsigned* eqZ)
{
    int t = threadIdx.x;
    __shared__ unsigned csum[1024], sfx[1024];
    int base = t * 64;
    unsigned s = 0;
    for (int i = 0; i < 64; i++) s += hist[base + i];
    csum[t] = s; sfx[t] = s;
    __syncthreads();
    for (int off = 1; off < 1024; off <<= 1) {
        unsigned v = (t + off < 1024) ? sfx[t + off] : 0u;
        __syncthreads();
        sfx[t] += v;
        __syncthreads();
    }
    int K = Ktarget - (prevAbove ? (int)(*prevAbove) : 0);
    unsigned run = sfx[t] - csum[t];   // strictly above this thread's bin range
    for (int i = 63; i >= 0; i--) {
        int bin = base + i;
        unsigned above = run;
        run += hist[bin];
        if ((int)above < K && (int)run >= K) {
            *outBin = (unsigned)bin;
            *outAbove = above;
            if (outT) {
                *outT = ((*hiBin) << 16) | (unsigned)bin;
                *outR = K - (int)above;
                *eqZ = 0u;
            }
        }
    }
    for (int i = 0; i < 64; i++) hist[base + i] = 0u;
}

__global__ void flags_kernel(const unsigned* __restrict__ key, int Ntot,
                             const unsigned* __restrict__ Tp, const int* __restrict__ rp,
                             unsigned* eq, int* flags)
{
    int i = blockIdx.x * blockDim.x + threadIdx.x;
    if (i >= Ntot) return;
    unsigned k = key[i], T = *Tp;
    int f = 0;
    if (k > T) f = 1;
    else if (k == T) { if ((int)atomicAdd(eq, 1u) < *rp) f = 1; }
    flags[i] = f;
}

__global__ void scan_partial(const int* __restrict__ flags, int Ntot, int* partial)
{
    __shared__ int sh[1024];
    int i = blockIdx.x * 1024 + threadIdx.x;
    sh[threadIdx.x] = (i < Ntot) ? flags[i] : 0;
    __syncthreads();
    for (int off = 512; off > 0; off >>= 1) {
        if (threadIdx.x < off) sh[threadIdx.x] += sh[threadIdx.x + off];
        __syncthreads();
    }
    if (threadIdx.x == 0) partial[blockIdx.x] = sh[0];
}

__global__ void scan_offsets(int* partial, int nb)
{
    if (threadIdx.x == 0) {
        int run = 0;
        for (int i = 0; i < nb; i++) { int v = partial[i]; partial[i] = run; run += v; }
    }
}

__global__ void scan_apply(const int* __restrict__ flags, int Ntot,
                           const int* __restrict__ partial, int* nm)
{
    __shared__ int sh[1024];
    int t = threadIdx.x;
    int i = blockIdx.x * 1024 + t;
    int f = (i < Ntot) ? flags[i] : 0;
    sh[t] = f;
    __syncthreads();
    for (int off = 1; off < 1024; off <<= 1) {
        int v = (t >= off) ? sh[t - off] : 0;
        __syncthreads();
        sh[t] += v;
        __syncthreads();
    }
    if (i < Ntot) nm[i] = f ? (partial[blockIdx.x] + sh[t] - f) : -1;
}

// pool0 gather: h0p[new] = relu((h*scale+shift) * score)   (96 threads, float4)
__global__ void gather0(const float* __restrict__ h, const float* __restrict__ scale,
                        const float* __restrict__ shift, const float* __restrict__ score,
                        const int* __restrict__ nm, float* hp)
{
    int n = blockIdx.x, t = threadIdx.x;
    int m = nm[n];
    if (m < 0) return;
    float sc = score[n];
    float4 hv = *(const float4*)(h + (size_t)n * FF0 + t * 4);
    float4 s4 = *(const float4*)(scale + t * 4);
    float4 b4 = *(const float4*)(shift + t * 4);
    float4 v;
    v.x = fmaxf((hv.x * s4.x + b4.x) * sc, 0.f);
    v.y = fmaxf((hv.y * s4.y + b4.y) * sc, 0.f);
    v.z = fmaxf((hv.z * s4.z + b4.z) * sc, 0.f);
    v.w = fmaxf((hv.w * s4.w + b4.w) * sc, 0.f);
    *(float4*)(hp + (size_t)m * FF0 + t * 4) = v;
}

__global__ void remap_edges(const int* __restrict__ src, const int* __restrict__ dst,
                            const int* __restrict__ nm, int* es, int* ed)
{
    int e = blockIdx.x * blockDim.x + threadIdx.x;
    if (e >= EE) return;
    int s = src[e], d = dst[e];
    int ns = -1, nd = -1;
    if (s != d) { ns = nm[s]; nd = nm[d]; }
    if (ns >= 0 && nd >= 0) { es[e] = ns; ed[e] = nd; }
    else { es[e] = -1; ed[e] = -1; }
}

// pool1 + global max fused, applying BN on the fly:
// gmax[c] = max over selected n of (h1[n,c]*scale[c]+shift[c]) * score1[n]
__global__ void maxreduce(const float* __restrict__ h1, const float* __restrict__ scale,
                          const float* __restrict__ shift, const float* __restrict__ score,
                          const int* __restrict__ flags, unsigned* gmax)
{
    int t = threadIdx.x;
    int base = blockIdx.x * 64;
    float sc_c = scale[t], sh_c = shift[t];
    float lm = -3.402823e38f;
    for (int r = 0; r < 64; r++) {
        int n = base + r;
        if (n >= K0N) break;
        if (flags[n])
            lm = fmaxf(lm, (h1[(size_t)n * DD + t] * sc_c + sh_c) * score[n]);
    }
    atomicMax(&gmax[t], ordf(lm));
}

// final MLP: relu(max) -> relu(@Wm1+bm1) -> @Wm2+bm2. 1 block, 256 threads.
__global__ void mlp_kernel(const unsigned* __restrict__ gmax,
                           const float* __restrict__ Wm1, const float* __restrict__ bm1,
                           const float* __restrict__ Wm2, const float* __restrict__ bm2,
                           float* out)
{
    __shared__ float v[128], mid[256];
    int t = threadIdx.x;
    if (t < 128) v[t] = fmaxf(unordf(gmax[t]), 0.f);
    __syncthreads();
    float a = bm1[t];
    for (int c = 0; c < 128; c++) a += v[c] * Wm1[c * 256 + t];
    mid[t] = fmaxf(a, 0.f);
    __syncthreads();
    if (t < 128) {
        float o = bm2[t];
        for (int j = 0; j < 256; j++) o += mid[j] * Wm2[j * 128 + t];
        out[t] = o;
    }
}

// ------------------------------------------------------------------
extern "C" void kernel_launch(void* const* d_in, const int* in_sizes, int n_in,
                              void* d_out, int out_size)
{
    (void)in_sizes; (void)n_in; (void)out_size;
    const float* x   = (const float*)d_in[0];
    const int*   ei  = (const int*)  d_in[1];
    const float* W0  = (const float*)d_in[3];
    const float* as0 = (const float*)d_in[4];
    const float* ad0 = (const float*)d_in[5];
    const float* b0  = (const float*)d_in[6];
    const float* g0  = (const float*)d_in[7];
    const float* be0 = (const float*)d_in[8];
    const float* p0  = (const float*)d_in[9];
    const float* W1  = (const float*)d_in[10];
    const float* as1 = (const float*)d_in[11];
    const float* ad1 = (const float*)d_in[12];
    const float* b1  = (const float*)d_in[13];
    const float* g1  = (const float*)d_in[14];
    const float* be1 = (const float*)d_in[15];
    const float* p1  = (const float*)d_in[16];
    const float* Wm1 = (const float*)d_in[17];
    const float* bm1 = (const float*)d_in[18];
    const float* Wm2 = (const float*)d_in[19];
    const float* bm2 = (const float*)d_in[20];
    const int* src = ei;
    const int* dst = ei + EE;
    float* out = (float*)d_out;

    float *xh0, *h0, *als0, *ald0, *den0, *score0, *bnsum, *bnsq, *scale, *shift, *pinv, *qv, *c0;
    float *h0p, *xh1, *h1, *als1, *ald1, *den1, *score1;
    unsigned *key0, *hist, *binhiP, *abovehiP, *binloP, *abovloP, *TP, *eqP, *key1, *gmax;
    int *rP, *flags, *partial, *nm, *es1, *ed1;

    cudaGetSymbolAddress((void**)&xh0, g_xh0);
    cudaGetSymbolAddress((void**)&h0, g_h0);
    cudaGetSymbolAddress((void**)&als0, g_als0);
    cudaGetSymbolAddress((void**)&ald0, g_ald0);
    cudaGetSymbolAddress((void**)&den0, g_den0);
    cudaGetSymbolAddress((void**)&score0, g_score0);
    cudaGetSymbolAddress((void**)&key0, g_key0);
    cudaGetSymbolAddress((void**)&bnsum, g_bnsum);
    cudaGetSymbolAddress((void**)&bnsq, g_bnsq);
    cudaGetSymbolAddress((void**)&scale, g_scale);
    cudaGetSymbolAddress((void**)&shift, g_shift);
    cudaGetSymbolAddress((void**)&qv, g_q);
    cudaGetSymbolAddress((void**)&c0, g_c0);
    cudaGetSymbolAddress((void**)&pinv, g_pinv);
    cudaGetSymbolAddress((void**)&hist, g_hist);
    cudaGetSymbolAddress((void**)&binhiP, g_binhi);
    cudaGetSymbolAddress((void**)&abovehiP, g_abovehi);
    cudaGetSymbolAddress((void**)&binloP, g_binlo);
    cudaGetSymbolAddress((void**)&abovloP, g_abovelo);
    cudaGetSymbolAddress((void**)&TP, g_T);
    cudaGetSymbolAddress((void**)&rP, g_r);
    cudaGetSymbolAddress((void**)&eqP, g_eq);
    cudaGetSymbolAddress((void**)&flags, g_flags);
    cudaGetSymbolAddress((void**)&partial, g_partial);
    cudaGetSymbolAddress((void**)&nm, g_nm);
    cudaGetSymbolAddress((void**)&h0p, g_h0p);
    cudaGetSymbolAddress((void**)&xh1, g_xh1);
    cudaGetSymbolAddress((void**)&h1, g_h1);
    cudaGetSymbolAddress((void**)&als1, g_als1);
    cudaGetSymbolAddress((void**)&ald1, g_ald1);
    cudaGetSymbolAddress((void**)&den1, g_den1);
    cudaGetSymbolAddress((void**)&es1, g_es1);
    cudaGetSymbolAddress((void**)&ed1, g_ed1);
    cudaGetSymbolAddress((void**)&score1, g_score1);
    cudaGetSymbolAddress((void**)&key1, g_key1);
    cudaGetSymbolAddress((void**)&gmax, g_gmax);

    // ---- GAT layer 0 ----
    {
        dim3 grid(FF0 / 128, NN / 128);
        gemm_kernel<<<grid, 256>>>(x, W0, xh0, NN, FF0, DD);
    }
    att_init<<<NN, 128>>>(xh0, as0, ad0, als0, ald0, den0, h0, 3);
    edge_fused<<<(EE + 7) / 8, 256>>>(src, dst, EE, als0, ald0, xh0, h0, den0, 3, 0);
    zero_bn<<<1, FF0>>>(bnsum, bnsq, FF0);
    epi_bn<<<(NN + 63) / 64, FF0>>>(h0, den0, b0, bnsum, bnsq, NN, FF0, 3);
    bn_final<<<1, 512>>>(bnsum, bnsq, g0, be0, scale, shift, p0, pinv, qv, c0,
                         (unsigned*)0, FF0, 1.0f / (float)NN);
    score_kernel<<<NN, 128>>>(h0, qv, c0, pinv, score0, key0, FF0);

    // ---- TopK pool 0 (exact K0 selection via 2-level radix histogram) ----
    hist_hi<<<(NN + 255) / 256, 256>>>(key0, NN, hist);
    find_bin<<<1, 1024>>>(hist, K0N, (const unsigned*)0, binhiP, abovehiP,
                          (const unsigned*)0, (unsigned*)0, (int*)0, (unsigned*)0);
    hist_lo<<<(NN + 255) / 256, 256>>>(key0, NN, hist, binhiP);
    find_bin<<<1, 1024>>>(hist, K0N, abovehiP, binloP, abovloP, binhiP, TP, rP, eqP);
    flags_kernel<<<(NN + 255) / 256, 256>>>(key0, NN, TP, rP, eqP, flags);
    scan_partial<<<NN / 1024, 1024>>>(flags, NN, partial);
    scan_offsets<<<1, 32>>>(partial, NN / 1024);
    scan_apply<<<NN / 1024, 1024>>>(flags, NN, partial, nm);
    gather0<<<NN, 96>>>(h0, scale, shift, score0, nm, h0p);
    remap_edges<<<(EE + 255) / 256, 256>>>(src, dst, nm, es1, ed1);

    // ---- GAT layer 1 ----
    {
        dim3 grid(DD / 128, (K0N + 127) / 128);
        gemm_kernel<<<grid, 256>>>(h0p, W1, xh1, K0N, DD, FF0);
    }
    att_init<<<K0N, 128>>>(xh1, as1, ad1, als1, ald1, den1, h1, 1);
    edge_fused<<<(EE + 7) / 8, 256>>>(es1, ed1, EE, als1, ald1, xh1, h1, den1, 1, 1);
    zero_bn<<<1, DD>>>(bnsum, bnsq, DD);
    epi_bn<<<(K0N + 63) / 64, DD>>>(h1, den1, b1, bnsum, bnsq, K0N, DD, 1);
    bn_final<<<1, 512>>>(bnsum, bnsq, g1, be1, scale, shift, p1, pinv, qv, c0,
                         gmax, DD, 1.0f / (float)K0N);
    score_kernel<<<K0N, 128>>>(h1, qv, c0, pinv, score1, key1, DD);

    // ---- TopK pool 1 (selection only) + fused global max ----
    hist_hi<<<(K0N + 255) / 256, 256>>>(key1, K0N, hist);
    find_bin<<<1, 1024>>>(hist, K1N, (const unsigned*)0, binhiP, abovehiP,
                          (const unsigned*)0, (unsigned*)0, (int*)0, (unsigned*)0);
    hist_lo<<<(K0N + 255) / 256, 256>>>(key1, K0N, hist, binhiP);
    find_bin<<<1, 1024>>>(hist, K1N, abovehiP, binloP, abovloP, binhiP, TP, rP, eqP);
    flags_kernel<<<(K0N + 255) / 256, 256>>>(key1, K0N, TP, rP, eqP, flags);
    maxreduce<<<(K0N + 63) / 64, 128>>>(h1, scale, shift, score1, flags, gmax);

    // ---- MLP head ----
    mlp_kernel<<<1, 256>>>(gmax, Wm1, bm1, Wm2, bm2, out);
}